// round 5
// baseline (speedup 1.0000x reference)
#include <cuda_runtime.h>
#include <math.h>

// ---------------- problem constants ----------------
#define NB    16          // batch
#define NCH   5           // channels
#define HIMG  256
#define WIMG  256
#define PP    8           // patch
#define SEQ   1024        // tokens per image (32*32)
#define NT    16384       // total tokens NB*SEQ
#define PD    320         // C*P*P
#define SF    64
#define ED    128
#define HS    512
#define NHD   4
#define HDIM  128
#define FF    2048
#define NE    6
#define NS    2
#define NLAY  4
#define NCLS  2

// ---------------- scratch (static device memory; no allocation allowed) ----------------
__device__ float g_t[NT * PD];
__device__ float g_z1[NT * SF];
__device__ float g_z[NT * ED];
__device__ float g_h[NT * HS];
__device__ float g_qkv[NT * 3 * HS];
__device__ float g_scores[(size_t)NB * NHD * SEQ * SEQ];   // 268 MB
__device__ float g_attno[NT * HS];
__device__ float g_a[NT * HS];
__device__ float g_spec[NT * HS];
__device__ float g_m[NT * HS];
__device__ float g_hid[NT * FF];                            // 134 MB
__device__ float g_sp[NT * NS];
__device__ int   g_eidx[NE * NT];
__device__ float g_ewt[NE * NT];
__device__ int   g_ecnt[NE];
__device__ float g_pool[NB * HS];

// ---------------- small helpers ----------------
__device__ __forceinline__ float warp_sum(float v) {
    #pragma unroll
    for (int o = 16; o; o >>= 1) v += __shfl_xor_sync(0xffffffffu, v, o);
    return v;
}
__device__ __forceinline__ float warp_max(float v) {
    #pragma unroll
    for (int o = 16; o; o >>= 1) v = fmaxf(v, __shfl_xor_sync(0xffffffffu, v, o));
    return v;
}

// ---------------- patch extraction ----------------
__global__ void patchify_kernel(const float* __restrict__ x) {
    int idx = blockIdx.x * blockDim.x + threadIdx.x;
    if (idx >= NT * PD) return;
    int n = idx / PD, f = idx % PD;
    int b = n / SEQ, s = n % SEQ;
    int sh = s >> 5, sw = s & 31;
    int c = f >> 6, r = f & 63;
    int pi = r >> 3, pj = r & 7;
    g_t[idx] = x[(((size_t)(b * NCH + c) * HIMG + (sh * PP + pi)) * WIMG) + (sw * PP + pj)];
}

// ---------------- positional encoding add ----------------
__global__ void add_pe_kernel() {
    int idx = blockIdx.x * blockDim.x + threadIdx.x;
    if (idx >= NT * ED) return;
    int n = idx >> 7, d = idx & 127;
    int s = n & (SEQ - 1);
    int i2 = d & ~1;
    float div = expf(-(float)i2 * (9.2103403719761836f / (float)ED));
    float arg = (float)s * div;
    float pe = (d & 1) ? cosf(arg) : sinf(arg);
    g_z[idx] += pe;
}

// ---------------- generic TN GEMM:  C[m,n] = act( sum_k A[m,k]*W[n,k] + bias[n] ) ----------------
// BM=BN=64, BK=32, 256 threads, 4x4 microtile.
// gidx: optional row gather on A. mcnt: optional dynamic row count (device).
// SCATTER: C[sidx[m]] += wv[m*ws] * (acc + bias[n])   (row-unique within a launch)
template<int ACT, int SCATTER>
__global__ __launch_bounds__(256) void gemm_tn(
    const float* __restrict__ A, const float* __restrict__ W,
    const float* __restrict__ bias, float* __restrict__ C,
    int M, int N, int K,
    const int* __restrict__ gidx, const int* __restrict__ mcnt,
    const int* __restrict__ sidx, const float* __restrict__ wv, int ws)
{
    int Mr = mcnt ? *mcnt : M;
    int m0 = blockIdx.y * 64;
    int n0 = blockIdx.x * 64;
    if (m0 >= Mr) return;

    __shared__ float As[32][64];
    __shared__ float Ws[32][64];
    __shared__ int   ridx[64];

    int tid = threadIdx.x;
    int tx = tid & 15, ty = tid >> 4;

    if (tid < 64) {
        int r = m0 + tid;
        if (r > Mr - 1) r = Mr - 1;
        ridx[tid] = gidx ? gidx[r] : r;
    }
    __syncthreads();

    float acc[4][4] = {};

    for (int kk = 0; kk < K; kk += 32) {
        #pragma unroll
        for (int i = 0; i < 2; i++) {
            int f = tid + i * 256;
            int r = f >> 3, c = (f & 7) * 4;
            float4 av = *(const float4*)&A[(size_t)ridx[r] * K + kk + c];
            As[c + 0][r] = av.x; As[c + 1][r] = av.y; As[c + 2][r] = av.z; As[c + 3][r] = av.w;
            float4 wv4 = *(const float4*)&W[(size_t)(n0 + r) * K + kk + c];
            Ws[c + 0][r] = wv4.x; Ws[c + 1][r] = wv4.y; Ws[c + 2][r] = wv4.z; Ws[c + 3][r] = wv4.w;
        }
        __syncthreads();
        #pragma unroll
        for (int k = 0; k < 32; k++) {
            float4 a4 = *(const float4*)&As[k][ty * 4];
            float4 b4 = *(const float4*)&Ws[k][tx * 4];
            float av[4] = {a4.x, a4.y, a4.z, a4.w};
            float bv[4] = {b4.x, b4.y, b4.z, b4.w};
            #pragma unroll
            for (int i = 0; i < 4; i++)
                #pragma unroll
                for (int j = 0; j < 4; j++)
                    acc[i][j] = fmaf(av[i], bv[j], acc[i][j]);
        }
        __syncthreads();
    }

    #pragma unroll
    for (int i = 0; i < 4; i++) {
        int m = m0 + ty * 4 + i;
        if (m >= Mr) break;
        if (SCATTER) {
            int row = sidx ? sidx[m] : m;
            float wgt = wv[(size_t)m * ws];
            float* crow = C + (size_t)row * N + n0 + tx * 4;
            #pragma unroll
            for (int j = 0; j < 4; j++) {
                int n = n0 + tx * 4 + j;
                crow[j] += wgt * (acc[i][j] + bias[n]);
            }
        } else {
            float* crow = C + (size_t)m * N + n0 + tx * 4;
            #pragma unroll
            for (int j = 0; j < 4; j++) {
                int n = n0 + tx * 4 + j;
                float v = acc[i][j] + bias[n];
                if (ACT == 1) v = fmaxf(v, 0.f);
                if (ACT == 2) v = 0.5f * v * (1.f + erff(v * 0.70710678118654752f));
                crow[j] = v;
            }
        }
    }
}

// ---------------- attention: scores = Q @ K^T (raw; scale applied in softmax) ----------------
__global__ __launch_bounds__(256) void attn_scores_kernel() {
    int z = blockIdx.z; int b = z >> 2; int h = z & 3;
    const float* Q  = g_qkv + (size_t)b * SEQ * (3 * HS) + h * HDIM;
    const float* Kp = Q + HS;
    float* Cs = g_scores + (size_t)z * SEQ * SEQ;
    int m0 = blockIdx.y * 64, n0 = blockIdx.x * 64;

    __shared__ float As[32][64];
    __shared__ float Ws[32][64];
    int tid = threadIdx.x;
    int tx = tid & 15, ty = tid >> 4;
    float acc[4][4] = {};

    for (int kk = 0; kk < HDIM; kk += 32) {
        #pragma unroll
        for (int i = 0; i < 2; i++) {
            int f = tid + i * 256;
            int r = f >> 3, c = (f & 7) * 4;
            float4 qa = *(const float4*)&Q[(size_t)(m0 + r) * (3 * HS) + kk + c];
            As[c + 0][r] = qa.x; As[c + 1][r] = qa.y; As[c + 2][r] = qa.z; As[c + 3][r] = qa.w;
            float4 ka = *(const float4*)&Kp[(size_t)(n0 + r) * (3 * HS) + kk + c];
            Ws[c + 0][r] = ka.x; Ws[c + 1][r] = ka.y; Ws[c + 2][r] = ka.z; Ws[c + 3][r] = ka.w;
        }
        __syncthreads();
        #pragma unroll
        for (int k = 0; k < 32; k++) {
            float4 a4 = *(const float4*)&As[k][ty * 4];
            float4 b4 = *(const float4*)&Ws[k][tx * 4];
            float av[4] = {a4.x, a4.y, a4.z, a4.w};
            float bv[4] = {b4.x, b4.y, b4.z, b4.w};
            #pragma unroll
            for (int i = 0; i < 4; i++)
                #pragma unroll
                for (int j = 0; j < 4; j++)
                    acc[i][j] = fmaf(av[i], bv[j], acc[i][j]);
        }
        __syncthreads();
    }
    #pragma unroll
    for (int i = 0; i < 4; i++) {
        int m = m0 + ty * 4 + i;
        float* crow = Cs + (size_t)m * SEQ + n0 + tx * 4;
        #pragma unroll
        for (int j = 0; j < 4; j++) crow[j] = acc[i][j];
    }
}

// ---------------- attention softmax (scale applied here) ----------------
__global__ __launch_bounds__(256) void attn_softmax_kernel() {
    size_t base = ((size_t)blockIdx.y * SEQ + blockIdx.x) * SEQ;
    float* row = g_scores + base;
    const float scale = 0.08838834764831845f;   // 1/sqrt(128)
    int tid = threadIdx.x;
    __shared__ float sm[8];

    float v[4];
    float mx = -1e30f;
    #pragma unroll
    for (int i = 0; i < 4; i++) { v[i] = row[tid + i * 256] * scale; mx = fmaxf(mx, v[i]); }
    mx = warp_max(mx);
    if ((tid & 31) == 0) sm[tid >> 5] = mx;
    __syncthreads();
    float bm = sm[0];
    #pragma unroll
    for (int i = 1; i < 8; i++) bm = fmaxf(bm, sm[i]);
    __syncthreads();

    float s = 0.f;
    #pragma unroll
    for (int i = 0; i < 4; i++) { v[i] = expf(v[i] - bm); s += v[i]; }
    s = warp_sum(s);
    if ((tid & 31) == 0) sm[tid >> 5] = s;
    __syncthreads();
    float tot = 0.f;
    #pragma unroll
    for (int i = 0; i < 8; i++) tot += sm[i];
    float inv = 1.f / tot;
    #pragma unroll
    for (int i = 0; i < 4; i++) row[tid + i * 256] = v[i] * inv;
}

// ---------------- attention AV: out = att @ V ----------------
__global__ __launch_bounds__(256) void attn_av_kernel() {
    int z = blockIdx.y; int b = z >> 2, h = z & 3;
    const float* V  = g_qkv + (size_t)b * SEQ * (3 * HS) + 2 * HS + h * HDIM;
    const float* Sc = g_scores + (size_t)z * SEQ * SEQ;
    int m0 = blockIdx.x * 64;

    __shared__ float As[32][64];     // [k][m]
    __shared__ float Vs[32][128];    // [k][d]
    int tid = threadIdx.x;
    int tx = tid & 15, ty = tid >> 4;
    float acc[4][8] = {};

    for (int kk = 0; kk < SEQ; kk += 32) {
        #pragma unroll
        for (int i = 0; i < 2; i++) {
            int f = tid + i * 256;
            int r = f >> 3, c = (f & 7) * 4;
            float4 a = *(const float4*)&Sc[(size_t)(m0 + r) * SEQ + kk + c];
            As[c + 0][r] = a.x; As[c + 1][r] = a.y; As[c + 2][r] = a.z; As[c + 3][r] = a.w;
        }
        #pragma unroll
        for (int i = 0; i < 4; i++) {
            int f = tid + i * 256;
            int k = f >> 5, c = (f & 31) * 4;
            *(float4*)&Vs[k][c] = *(const float4*)&V[(size_t)(kk + k) * (3 * HS) + c];
        }
        __syncthreads();
        #pragma unroll
        for (int k = 0; k < 32; k++) {
            float4 a4 = *(const float4*)&As[k][ty * 4];
            float4 v0 = *(const float4*)&Vs[k][tx * 8];
            float4 v1 = *(const float4*)&Vs[k][tx * 8 + 4];
            float av[4] = {a4.x, a4.y, a4.z, a4.w};
            float bv[8] = {v0.x, v0.y, v0.z, v0.w, v1.x, v1.y, v1.z, v1.w};
            #pragma unroll
            for (int i = 0; i < 4; i++)
                #pragma unroll
                for (int j = 0; j < 8; j++)
                    acc[i][j] = fmaf(av[i], bv[j], acc[i][j]);
        }
        __syncthreads();
    }
    #pragma unroll
    for (int i = 0; i < 4; i++) {
        int q = m0 + ty * 4 + i;
        float* orow = g_attno + (size_t)(b * SEQ + q) * HS + h * HDIM + tx * 8;
        #pragma unroll
        for (int j = 0; j < 8; j++) orow[j] = acc[i][j];
    }
}

// ---------------- fused residual-add + layernorm: O = LN(X + Y) ----------------
__global__ __launch_bounds__(128) void ln_add_kernel(
    const float* __restrict__ X, const float* __restrict__ Y,
    const float* __restrict__ gam, const float* __restrict__ bet,
    float* __restrict__ O)
{
    size_t base = (size_t)blockIdx.x * HS;
    int tid = threadIdx.x;
    __shared__ float sm[4];
    float v[4];
    #pragma unroll
    for (int i = 0; i < 4; i++) { int d = tid + i * 128; v[i] = X[base + d] + Y[base + d]; }
    float s = v[0] + v[1] + v[2] + v[3];
    s = warp_sum(s);
    if ((tid & 31) == 0) sm[tid >> 5] = s;
    __syncthreads();
    float mean = (sm[0] + sm[1] + sm[2] + sm[3]) * (1.f / HS);
    __syncthreads();
    float q = 0.f;
    #pragma unroll
    for (int i = 0; i < 4; i++) { float d = v[i] - mean; q += d * d; }
    q = warp_sum(q);
    if ((tid & 31) == 0) sm[tid >> 5] = q;
    __syncthreads();
    float var = (sm[0] + sm[1] + sm[2] + sm[3]) * (1.f / HS);
    float inv = rsqrtf(var + 1e-5f);
    #pragma unroll
    for (int i = 0; i < 4; i++) {
        int d = tid + i * 128;
        O[base + d] = (v[i] - mean) * inv * gam[d] + bet[d];
    }
}

// ---------------- specific-MoE router: softmax over 6, top-2, compact per expert ----------------
__global__ __launch_bounds__(256) void route_spec_kernel(const float* __restrict__ rw) {
    int warp = threadIdx.x >> 5, lane = threadIdx.x & 31;
    int token = blockIdx.x * 8 + warp;
    const float* hrow = g_h + (size_t)token * HS;
    float hv[16];
    #pragma unroll
    for (int j = 0; j < 16; j++) hv[j] = hrow[lane + j * 32];
    float logit[NE];
    #pragma unroll
    for (int e = 0; e < NE; e++) {
        const float* w = rw + e * HS;
        float p = 0.f;
        #pragma unroll
        for (int j = 0; j < 16; j++) p = fmaf(hv[j], w[lane + j * 32], p);
        logit[e] = warp_sum(p);
    }
    if (lane == 0) {
        float mx = logit[0];
        #pragma unroll
        for (int e = 1; e < NE; e++) mx = fmaxf(mx, logit[e]);
        float pr[NE], s = 0.f;
        #pragma unroll
        for (int e = 0; e < NE; e++) { pr[e] = expf(logit[e] - mx); s += pr[e]; }
        #pragma unroll
        for (int e = 0; e < NE; e++) pr[e] /= s;
        int i1 = 0;
        #pragma unroll
        for (int e = 1; e < NE; e++) if (pr[e] > pr[i1]) i1 = e;
        int i2 = (i1 == 0) ? 1 : 0;
        #pragma unroll
        for (int e = 0; e < NE; e++) if (e != i1 && pr[e] > pr[i2]) i2 = e;
        float den = pr[i1] + pr[i2] + 1e-9f;
        float w1 = pr[i1] / den, w2 = pr[i2] / den;
        int p1 = atomicAdd(&g_ecnt[i1], 1);
        g_eidx[i1 * NT + p1] = token; g_ewt[i1 * NT + p1] = w1;
        int p2 = atomicAdd(&g_ecnt[i2], 1);
        g_eidx[i2 * NT + p2] = token; g_ewt[i2 * NT + p2] = w2;
    }
}

// ---------------- shared-MoE router: softmax over 2 ----------------
__global__ __launch_bounds__(256) void route_shared_kernel(const float* __restrict__ rw) {
    int warp = threadIdx.x >> 5, lane = threadIdx.x & 31;
    int token = blockIdx.x * 8 + warp;
    const float* hrow = g_h + (size_t)token * HS;
    float hv[16];
    #pragma unroll
    for (int j = 0; j < 16; j++) hv[j] = hrow[lane + j * 32];
    float logit[NS];
    #pragma unroll
    for (int e = 0; e < NS; e++) {
        const float* w = rw + e * HS;
        float p = 0.f;
        #pragma unroll
        for (int j = 0; j < 16; j++) p = fmaf(hv[j], w[lane + j * 32], p);
        logit[e] = warp_sum(p);
    }
    if (lane == 0) {
        float mx = fmaxf(logit[0], logit[1]);
        float e0 = expf(logit[0] - mx), e1 = expf(logit[1] - mx);
        float inv = 1.f / (e0 + e1);
        g_sp[token * NS + 0] = e0 * inv;
        g_sp[token * NS + 1] = e1 * inv;
    }
}

// ---------------- mean pool over sequence ----------------
__global__ void pool_mean_kernel() {
    int b = blockIdx.x, d = threadIdx.x;  // 512 threads
    float s = 0.f;
    for (int t = 0; t < SEQ; t++) s += g_h[((size_t)b * SEQ + t) * HS + d];
    g_pool[b * HS + d] = s * (1.f / SEQ);
}

// ---------------- classifier head ----------------
__global__ __launch_bounds__(128) void cls_head_kernel(
    const float* __restrict__ w, const float* __restrict__ bias, float* __restrict__ out)
{
    int n = blockIdx.x, b = blockIdx.y;
    int tid = threadIdx.x;
    __shared__ float sm[4];
    float p = 0.f;
    for (int j = tid; j < HS; j += 128) p = fmaf(g_pool[b * HS + j], w[n * HS + j], p);
    p = warp_sum(p);
    if ((tid & 31) == 0) sm[tid >> 5] = p;
    __syncthreads();
    if (tid == 0) out[b * NCLS + n] = sm[0] + sm[1] + sm[2] + sm[3] + bias[n];
}

// ---------------- host-side launch helpers ----------------
static void launch_gemm(int act, const float* A, const float* W, const float* bias,
                        float* C, int M, int N, int K,
                        const int* gidx = nullptr, const int* mcnt = nullptr)
{
    dim3 grid(N / 64, (M + 63) / 64);
    if (act == 0)      gemm_tn<0, 0><<<grid, 256>>>(A, W, bias, C, M, N, K, gidx, mcnt, nullptr, nullptr, 0);
    else if (act == 1) gemm_tn<1, 0><<<grid, 256>>>(A, W, bias, C, M, N, K, gidx, mcnt, nullptr, nullptr, 0);
    else               gemm_tn<2, 0><<<grid, 256>>>(A, W, bias, C, M, N, K, gidx, mcnt, nullptr, nullptr, 0);
}

static void launch_gemm_scatter(const float* A, const float* W, const float* bias,
                                float* C, int M, int N, int K,
                                const int* mcnt, const int* sidx,
                                const float* wv, int ws)
{
    dim3 grid(N / 64, (M + 63) / 64);
    gemm_tn<0, 1><<<grid, 256>>>(A, W, bias, C, M, N, K, nullptr, mcnt, sidx, wv, ws);
}

extern "C" void kernel_launch(void* const* d_in, const int* in_sizes, int n_in,
                              void* d_out, int out_size)
{
    const float* x         = (const float*)d_in[0];
    const float* tok_w1    = (const float*)d_in[1];
    const float* tok_b1    = (const float*)d_in[2];
    const float* tok_w2    = (const float*)d_in[3];
    const float* tok_b2    = (const float*)d_in[4];
    const float* proj_w    = (const float*)d_in[5];
    const float* proj_b    = (const float*)d_in[6];
    const float* attn_wqkv = (const float*)d_in[7];
    const float* attn_bqkv = (const float*)d_in[8];
    const float* attn_wo   = (const float*)d_in[9];
    const float* attn_bo   = (const float*)d_in[10];
    const float* ln1_g     = (const float*)d_in[11];
    const float* ln1_b     = (const float*)d_in[12];
    const float* spec_rw   = (const float*)d_in[13];
    const float* spec_f1w  = (const float*)d_in[14];
    const float* spec_f1b  = (const float*)d_in[15];
    const float* spec_f2w  = (const float*)d_in[16];
    const float* spec_f2b  = (const float*)d_in[17];
    const float* shr_rw    = (const float*)d_in[18];
    const float* shr_f1w   = (const float*)d_in[19];
    const float* shr_f1b   = (const float*)d_in[20];
    const float* shr_f2w   = (const float*)d_in[21];
    const float* shr_f2b   = (const float*)d_in[22];
    const float* lnm_g     = (const float*)d_in[23];
    const float* lnm_b     = (const float*)d_in[24];
    const float* ln2_g     = (const float*)d_in[25];
    const float* ln2_b     = (const float*)d_in[26];
    const float* cls_w     = (const float*)d_in[27];
    const float* cls_b     = (const float*)d_in[28];
    float* out = (float*)d_out;

    float *pt, *pz1, *pz, *ph, *pattno, *pa, *pspec, *pm, *phid, *psp, *pewt;
    int *peidx, *pecnt;
    cudaGetSymbolAddress((void**)&pt, g_t);
    cudaGetSymbolAddress((void**)&pz1, g_z1);
    cudaGetSymbolAddress((void**)&pz, g_z);
    cudaGetSymbolAddress((void**)&ph, g_h);
    float* pqkv; cudaGetSymbolAddress((void**)&pqkv, g_qkv);
    cudaGetSymbolAddress((void**)&pattno, g_attno);
    cudaGetSymbolAddress((void**)&pa, g_a);
    cudaGetSymbolAddress((void**)&pspec, g_spec);
    cudaGetSymbolAddress((void**)&pm, g_m);
    cudaGetSymbolAddress((void**)&phid, g_hid);
    cudaGetSymbolAddress((void**)&psp, g_sp);
    cudaGetSymbolAddress((void**)&pewt, g_ewt);
    cudaGetSymbolAddress((void**)&peidx, g_eidx);
    cudaGetSymbolAddress((void**)&pecnt, g_ecnt);

    // ---- tokenizer + projection ----
    patchify_kernel<<<(NT * PD + 255) / 256, 256>>>(x);
    launch_gemm(1, pt,  tok_w1, tok_b1, pz1, NT, SF, PD);
    launch_gemm(1, pz1, tok_w2, tok_b2, pz,  NT, ED, SF);
    add_pe_kernel<<<(NT * ED + 255) / 256, 256>>>();
    launch_gemm(0, pz,  proj_w, proj_b, ph,  NT, HS, ED);

    // ---- transformer layers ----
    for (int l = 0; l < NLAY; l++) {
        // attention
        launch_gemm(0, ph, attn_wqkv + (size_t)l * 3 * HS * HS, attn_bqkv + (size_t)l * 3 * HS,
                    pqkv, NT, 3 * HS, HS);
        attn_scores_kernel<<<dim3(SEQ / 64, SEQ / 64, NB * NHD), 256>>>();
        attn_softmax_kernel<<<dim3(SEQ, NB * NHD), 256>>>();
        attn_av_kernel<<<dim3(SEQ / 64, NB * NHD), 256>>>();
        launch_gemm(0, pattno, attn_wo + (size_t)l * HS * HS, attn_bo + (size_t)l * HS,
                    pa, NT, HS, HS);
        ln_add_kernel<<<NT, 128>>>(ph, pa, ln1_g + l * HS, ln1_b + l * HS, ph);

        // MoE
        cudaMemsetAsync(pecnt, 0, NE * sizeof(int));
        cudaMemsetAsync(pspec, 0, (size_t)NT * HS * sizeof(float));
        route_spec_kernel<<<NT / 8, 256>>>(spec_rw + (size_t)l * NE * HS);
        for (int e = 0; e < NE; e++) {
            const float* f1w = spec_f1w + (size_t)(l * NE + e) * FF * HS;
            const float* f1b = spec_f1b + (size_t)(l * NE + e) * FF;
            const float* f2w = spec_f2w + (size_t)(l * NE + e) * HS * FF;
            const float* f2b = spec_f2b + (size_t)(l * NE + e) * HS;
            launch_gemm(2, ph, f1w, f1b, phid, NT, FF, HS, peidx + e * NT, pecnt + e);
            launch_gemm_scatter(phid, f2w, f2b, pspec, NT, HS, FF,
                                pecnt + e, peidx + e * NT, pewt + e * NT, 1);
        }
        route_shared_kernel<<<NT / 8, 256>>>(shr_rw + (size_t)l * NS * HS);
        for (int e = 0; e < NS; e++) {
            const float* f1w = shr_f1w + (size_t)(l * NS + e) * FF * HS;
            const float* f1b = shr_f1b + (size_t)(l * NS + e) * FF;
            const float* f2w = shr_f2w + (size_t)(l * NS + e) * HS * FF;
            const float* f2b = shr_f2b + (size_t)(l * NS + e) * HS;
            launch_gemm(2, ph, f1w, f1b, phid, NT, FF, HS);
            launch_gemm_scatter(phid, f2w, f2b, pspec, NT, HS, FF,
                                nullptr, nullptr, psp + e, NS);
        }
        ln_add_kernel<<<NT, 128>>>(ph, pspec, lnm_g + l * HS, lnm_b + l * HS, pm);
        ln_add_kernel<<<NT, 128>>>(ph, pm, ln2_g + l * HS, ln2_b + l * HS, ph);
    }

    // ---- head ----
    pool_mean_kernel<<<NB, HS>>>();
    cls_head_kernel<<<dim3(NCLS, NB), 128>>>(cls_w, cls_b, out);
}

// round 7
// speedup vs baseline: 2.0786x; 2.0786x over previous
#include <cuda_runtime.h>
#include <cuda_bf16.h>
#include <stdint.h>
#include <math.h>

// ---------------- problem constants ----------------
#define NB    16
#define NCH   5
#define HIMG  256
#define WIMG  256
#define PP    8
#define SEQ   1024
#define NT    16384
#define PD    320
#define SF    64
#define ED    128
#define HS    512
#define NHD   4
#define HDIM  128
#define FF    2048
#define NE    6
#define NS    2
#define NLAY  4
#define NCLS  2

#define TS    40   // smem tile k-stride (bf16 elems): 80B rows, 16B aligned, conflict-free

// ---------------- scratch ----------------
__device__ float g_t[NT * PD];
__device__ float g_z1[NT * SF];
__device__ float g_z[NT * ED];
__device__ float g_h[NT * HS];
__device__ float g_qkv[NT * 3 * HS];
__device__ float g_scores[(size_t)NB * NHD * SEQ * SEQ];
__device__ float g_attno[NT * HS];
__device__ float g_a[NT * HS];
__device__ float g_spec[NT * HS];
__device__ float g_m[NT * HS];
__device__ float g_hid[NT * FF];
__device__ float g_sp[NT * NS];
__device__ int   g_eidx[NE * NT];
__device__ float g_ewt[NE * NT];
__device__ int   g_ecnt[NE];
__device__ float g_pool[NB * HS];

// ---------------- helpers ----------------
__device__ __forceinline__ float warp_sum(float v) {
    #pragma unroll
    for (int o = 16; o; o >>= 1) v += __shfl_xor_sync(0xffffffffu, v, o);
    return v;
}
__device__ __forceinline__ float warp_max(float v) {
    #pragma unroll
    for (int o = 16; o; o >>= 1) v = fmaxf(v, __shfl_xor_sync(0xffffffffu, v, o));
    return v;
}

__device__ __forceinline__ void ldsm4(unsigned int* r, unsigned int addr) {
    asm volatile("ldmatrix.sync.aligned.m8n8.x4.shared.b16 {%0,%1,%2,%3}, [%4];"
                 : "=r"(r[0]), "=r"(r[1]), "=r"(r[2]), "=r"(r[3]) : "r"(addr));
}
__device__ __forceinline__ void mma16816(float* c, const unsigned int* a, const unsigned int* b) {
    asm volatile("mma.sync.aligned.m16n8k16.row.col.f32.bf16.bf16.f32 "
                 "{%0,%1,%2,%3}, {%4,%5,%6,%7}, {%8,%9}, {%0,%1,%2,%3};"
                 : "+f"(c[0]), "+f"(c[1]), "+f"(c[2]), "+f"(c[3])
                 : "r"(a[0]), "r"(a[1]), "r"(a[2]), "r"(a[3]), "r"(b[0]), "r"(b[1]));
}

// split fp32 -> (hi, lo) bf16 pair, paired stores
__device__ __forceinline__ void split_store(float a, float b,
                                            __nv_bfloat16* hi, __nv_bfloat16* lo) {
    __nv_bfloat16 ha = __float2bfloat16(a);
    __nv_bfloat16 hb = __float2bfloat16(b);
    __nv_bfloat162 hp; hp.x = ha; hp.y = hb;
    __nv_bfloat162 lp;
    lp.x = __float2bfloat16(a - __bfloat162float(ha));
    lp.y = __float2bfloat16(b - __bfloat162float(hb));
    *(__nv_bfloat162*)hi = hp;
    *(__nv_bfloat162*)lo = lp;
}

// ---------------- patch extraction ----------------
__global__ void patchify_kernel(const float* __restrict__ x) {
    int idx = blockIdx.x * blockDim.x + threadIdx.x;
    if (idx >= NT * PD) return;
    int n = idx / PD, f = idx % PD;
    int b = n / SEQ, s = n % SEQ;
    int sh = s >> 5, sw = s & 31;
    int c = f >> 6, r = f & 63;
    int pi = r >> 3, pj = r & 7;
    g_t[idx] = x[(((size_t)(b * NCH + c) * HIMG + (sh * PP + pi)) * WIMG) + (sw * PP + pj)];
}

// ---------------- positional encoding add ----------------
__global__ void add_pe_kernel() {
    int idx = blockIdx.x * blockDim.x + threadIdx.x;
    if (idx >= NT * ED) return;
    int n = idx >> 7, d = idx & 127;
    int s = n & (SEQ - 1);
    int i2 = d & ~1;
    float div = expf(-(float)i2 * (9.2103403719761836f / (float)ED));
    float arg = (float)s * div;
    float pe = (d & 1) ? cosf(arg) : sinf(arg);
    g_z[idx] += pe;
}

// ================= tensor-core GEMM =================
// MODE 0: C[m,n] = act(sum_k A[m,k] W[n,k] + bias[n]), optional gather/scatter/dyn-M
// MODE 1: per z=(b,h): scores[z][q][k'] = Q[q,:]·K[k',:]
// MODE 2: per z=(b,h): attno[b*SEQ+q][h*128+d] = S[q,:]·V[:,d]
// BM=128 BN=64 BK=32, 256 threads, 8 warps (4x2), warp tile 32x32, 3-MMA bf16 split.
template<int MODE, int ACT, int SCATTER>
__global__ __launch_bounds__(256) void tgemm(
    const float* __restrict__ A, const float* __restrict__ W,
    const float* __restrict__ bias, float* __restrict__ C,
    int M, int N, int K,
    const int* __restrict__ gidx, const int* __restrict__ mcnt,
    const int* __restrict__ sidx, const float* __restrict__ wv, int ws)
{
    const float* Ab; const float* Wb; float* Cb;
    int lda, ldw, ldc;
    if (MODE == 1) {
        int z = blockIdx.z; int b = z >> 2, h = z & 3;
        Ab = A + (size_t)b * SEQ * (3 * HS) + h * HDIM;          lda = 3 * HS;
        Wb = A + (size_t)b * SEQ * (3 * HS) + HS + h * HDIM;     ldw = 3 * HS;
        Cb = C + (size_t)z * SEQ * SEQ;                           ldc = SEQ;
    } else if (MODE == 2) {
        int z = blockIdx.z; int b = z >> 2, h = z & 3;
        Ab = A + (size_t)z * SEQ * SEQ;                           lda = SEQ;
        Wb = W + (size_t)b * SEQ * (3 * HS) + 2 * HS + h * HDIM;  ldw = 3 * HS;
        Cb = C + (size_t)b * SEQ * HS + h * HDIM;                 ldc = HS;
    } else {
        Ab = A; Wb = W; Cb = C; lda = K; ldw = K; ldc = N;
    }

    int Mr = (MODE == 0 && mcnt) ? *mcnt : M;
    int m0 = blockIdx.y * 128;
    int n0 = blockIdx.x * 64;
    if (m0 >= Mr) return;

    __shared__ __align__(16) __nv_bfloat16 As_hi[128 * TS];
    __shared__ __align__(16) __nv_bfloat16 As_lo[128 * TS];
    __shared__ __align__(16) __nv_bfloat16 Ws_hi[64 * TS];
    __shared__ __align__(16) __nv_bfloat16 Ws_lo[64 * TS];
    __shared__ int ridx[128];

    int tid = threadIdx.x;
    int warp = tid >> 5, L = tid & 31;
    int warp_m = warp >> 1, warp_n = warp & 1;

    if (tid < 128) {
        int r = m0 + tid;
        if (r > Mr - 1) r = Mr - 1;
        ridx[tid] = (MODE == 0 && gidx) ? gidx[r] : r;
    }
    __syncthreads();

    // ldmatrix per-lane offsets (element units)
    int rowA = ((L >> 3) & 1) * 8 + (L & 7);
    int kA   = ((L >> 4) & 1) * 8;
    int rowB = ((L >> 4) & 1) * 8 + (L & 7);
    int kB   = ((L >> 3) & 1) * 8;
    int offA[2], offB[2];
    #pragma unroll
    for (int mi = 0; mi < 2; mi++) offA[mi] = (warp_m * 32 + mi * 16 + rowA) * TS + kA;
    #pragma unroll
    for (int nb = 0; nb < 2; nb++) offB[nb] = (warp_n * 32 + nb * 16 + rowB) * TS + kB;

    unsigned int as_hi_b = (unsigned int)__cvta_generic_to_shared(As_hi);
    unsigned int as_lo_b = (unsigned int)__cvta_generic_to_shared(As_lo);
    unsigned int ws_hi_b = (unsigned int)__cvta_generic_to_shared(Ws_hi);
    unsigned int ws_lo_b = (unsigned int)__cvta_generic_to_shared(Ws_lo);

    float acc[2][4][4] = {};

    for (int kk = 0; kk < K; kk += 32) {
        // ---- stage A tile (128x32) ----
        #pragma unroll
        for (int i = 0; i < 4; i++) {
            int f = tid + i * 256;
            int r = f >> 3, c4 = (f & 7) * 4;
            const float* src = Ab + (size_t)ridx[r] * lda + kk + c4;
            float4 v = *(const float4*)src;
            split_store(v.x, v.y, &As_hi[r * TS + c4],     &As_lo[r * TS + c4]);
            split_store(v.z, v.w, &As_hi[r * TS + c4 + 2], &As_lo[r * TS + c4 + 2]);
        }
        // ---- stage W tile (64x32) ----
        if (MODE == 2) {
            #pragma unroll
            for (int i = 0; i < 2; i++) {
                int f = tid + i * 256;
                int kr = f >> 4, c4 = (f & 15) * 4;
                const float* src = Wb + (size_t)(kk + kr) * ldw + n0 + c4;
                float4 v = *(const float4*)src;
                float vs[4] = {v.x, v.y, v.z, v.w};
                #pragma unroll
                for (int j = 0; j < 4; j++) {
                    __nv_bfloat16 h = __float2bfloat16(vs[j]);
                    Ws_hi[(c4 + j) * TS + kr] = h;
                    Ws_lo[(c4 + j) * TS + kr] = __float2bfloat16(vs[j] - __bfloat162float(h));
                }
            }
        } else {
            #pragma unroll
            for (int i = 0; i < 2; i++) {
                int f = tid + i * 256;
                int r = f >> 3, c4 = (f & 7) * 4;
                const float* src = Wb + (size_t)(n0 + r) * ldw + kk + c4;
                float4 v = *(const float4*)src;
                split_store(v.x, v.y, &Ws_hi[r * TS + c4],     &Ws_lo[r * TS + c4]);
                split_store(v.z, v.w, &Ws_hi[r * TS + c4 + 2], &Ws_lo[r * TS + c4 + 2]);
            }
        }
        __syncthreads();

        // ---- 2 x k16 MMA steps ----
        #pragma unroll
        for (int ks = 0; ks < 32; ks += 16) {
            unsigned int ah[2][4], al[2][4], bh[2][4], bl[2][4];
            #pragma unroll
            for (int mi = 0; mi < 2; mi++) {
                ldsm4(ah[mi], as_hi_b + (unsigned int)(offA[mi] + ks) * 2u);
                ldsm4(al[mi], as_lo_b + (unsigned int)(offA[mi] + ks) * 2u);
            }
            #pragma unroll
            for (int nb = 0; nb < 2; nb++) {
                ldsm4(bh[nb], ws_hi_b + (unsigned int)(offB[nb] + ks) * 2u);
                ldsm4(bl[nb], ws_lo_b + (unsigned int)(offB[nb] + ks) * 2u);
            }
            #pragma unroll
            for (int mi = 0; mi < 2; mi++)
                #pragma unroll
                for (int ni = 0; ni < 4; ni++) {
                    int nb = ni >> 1, sel = (ni & 1) * 2;
                    mma16816(acc[mi][ni], ah[mi], &bh[nb][sel]);
                    mma16816(acc[mi][ni], ah[mi], &bl[nb][sel]);
                    mma16816(acc[mi][ni], al[mi], &bh[nb][sel]);
                }
        }
        __syncthreads();
    }

    // ---- epilogue ----
    #pragma unroll
    for (int mi = 0; mi < 2; mi++) {
        #pragma unroll
        for (int hh = 0; hh < 2; hh++) {
            int m = m0 + warp_m * 32 + mi * 16 + (L >> 2) + hh * 8;
            if (m >= Mr) continue;
            int srow = 0; float wgt = 0.f;
            if (SCATTER) {
                srow = sidx ? sidx[m] : m;
                wgt = wv[(size_t)m * ws];
            }
            #pragma unroll
            for (int ni = 0; ni < 4; ni++) {
                int n = n0 + warp_n * 32 + ni * 8 + (L & 3) * 2;
                float v0 = acc[mi][ni][hh * 2 + 0];
                float v1 = acc[mi][ni][hh * 2 + 1];
                if (MODE == 0 && bias) { v0 += bias[n]; v1 += bias[n + 1]; }
                if (ACT == 1) { v0 = fmaxf(v0, 0.f); v1 = fmaxf(v1, 0.f); }
                if (ACT == 2) {
                    v0 = 0.5f * v0 * (1.f + erff(v0 * 0.70710678118654752f));
                    v1 = 0.5f * v1 * (1.f + erff(v1 * 0.70710678118654752f));
                }
                if (SCATTER) {
                    float* dst = Cb + (size_t)srow * ldc + n;
                    dst[0] += wgt * v0;
                    dst[1] += wgt * v1;
                } else {
                    float* dst = Cb + (size_t)m * ldc + n;
                    dst[0] = v0; dst[1] = v1;
                }
            }
        }
    }
}

// ---------------- attention softmax (scale applied here) ----------------
__global__ __launch_bounds__(256) void attn_softmax_kernel() {
    size_t base = ((size_t)blockIdx.y * SEQ + blockIdx.x) * SEQ;
    float* row = g_scores + base;
    const float scale = 0.08838834764831845f;
    int tid = threadIdx.x;
    __shared__ float sm[8];

    float v[4];
    float mx = -1e30f;
    #pragma unroll
    for (int i = 0; i < 4; i++) { v[i] = row[tid + i * 256] * scale; mx = fmaxf(mx, v[i]); }
    mx = warp_max(mx);
    if ((tid & 31) == 0) sm[tid >> 5] = mx;
    __syncthreads();
    float bm = sm[0];
    #pragma unroll
    for (int i = 1; i < 8; i++) bm = fmaxf(bm, sm[i]);
    __syncthreads();

    float s = 0.f;
    #pragma unroll
    for (int i = 0; i < 4; i++) { v[i] = expf(v[i] - bm); s += v[i]; }
    s = warp_sum(s);
    if ((tid & 31) == 0) sm[tid >> 5] = s;
    __syncthreads();
    float tot = 0.f;
    #pragma unroll
    for (int i = 0; i < 8; i++) tot += sm[i];
    float inv = 1.f / tot;
    #pragma unroll
    for (int i = 0; i < 4; i++) row[tid + i * 256] = v[i] * inv;
}

// ---------------- fused residual-add + layernorm ----------------
__global__ __launch_bounds__(128) void ln_add_kernel(
    const float* __restrict__ X, const float* __restrict__ Y,
    const float* __restrict__ gam, const float* __restrict__ bet,
    float* __restrict__ O)
{
    size_t base = (size_t)blockIdx.x * HS;
    int tid = threadIdx.x;
    __shared__ float sm[4];
    float v[4];
    #pragma unroll
    for (int i = 0; i < 4; i++) { int d = tid + i * 128; v[i] = X[base + d] + Y[base + d]; }
    float s = v[0] + v[1] + v[2] + v[3];
    s = warp_sum(s);
    if ((tid & 31) == 0) sm[tid >> 5] = s;
    __syncthreads();
    float mean = (sm[0] + sm[1] + sm[2] + sm[3]) * (1.f / HS);
    __syncthreads();
    float q = 0.f;
    #pragma unroll
    for (int i = 0; i < 4; i++) { float d = v[i] - mean; q += d * d; }
    q = warp_sum(q);
    if ((tid & 31) == 0) sm[tid >> 5] = q;
    __syncthreads();
    float var = (sm[0] + sm[1] + sm[2] + sm[3]) * (1.f / HS);
    float inv = rsqrtf(var + 1e-5f);
    #pragma unroll
    for (int i = 0; i < 4; i++) {
        int d = tid + i * 128;
        O[base + d] = (v[i] - mean) * inv * gam[d] + bet[d];
    }
}

// ---------------- routers ----------------
__global__ __launch_bounds__(256) void route_spec_kernel(const float* __restrict__ rw) {
    int warp = threadIdx.x >> 5, lane = threadIdx.x & 31;
    int token = blockIdx.x * 8 + warp;
    const float* hrow = g_h + (size_t)token * HS;
    float hv[16];
    #pragma unroll
    for (int j = 0; j < 16; j++) hv[j] = hrow[lane + j * 32];
    float logit[NE];
    #pragma unroll
    for (int e = 0; e < NE; e++) {
        const float* w = rw + e * HS;
        float p = 0.f;
        #pragma unroll
        for (int j = 0; j < 16; j++) p = fmaf(hv[j], w[lane + j * 32], p);
        logit[e] = warp_sum(p);
    }
    if (lane == 0) {
        float mx = logit[0];
        #pragma unroll
        for (int e = 1; e < NE; e++) mx = fmaxf(mx, logit[e]);
        float pr[NE], s = 0.f;
        #pragma unroll
        for (int e = 0; e < NE; e++) { pr[e] = expf(logit[e] - mx); s += pr[e]; }
        #pragma unroll
        for (int e = 0; e < NE; e++) pr[e] /= s;
        int i1 = 0;
        #pragma unroll
        for (int e = 1; e < NE; e++) if (pr[e] > pr[i1]) i1 = e;
        int i2 = (i1 == 0) ? 1 : 0;
        #pragma unroll
        for (int e = 0; e < NE; e++) if (e != i1 && pr[e] > pr[i2]) i2 = e;
        float den = pr[i1] + pr[i2] + 1e-9f;
        float w1 = pr[i1] / den, w2 = pr[i2] / den;
        int p1 = atomicAdd(&g_ecnt[i1], 1);
        g_eidx[i1 * NT + p1] = token; g_ewt[i1 * NT + p1] = w1;
        int p2 = atomicAdd(&g_ecnt[i2], 1);
        g_eidx[i2 * NT + p2] = token; g_ewt[i2 * NT + p2] = w2;
    }
}

__global__ __launch_bounds__(256) void route_shared_kernel(const float* __restrict__ rw) {
    int warp = threadIdx.x >> 5, lane = threadIdx.x & 31;
    int token = blockIdx.x * 8 + warp;
    const float* hrow = g_h + (size_t)token * HS;
    float hv[16];
    #pragma unroll
    for (int j = 0; j < 16; j++) hv[j] = hrow[lane + j * 32];
    float logit[NS];
    #pragma unroll
    for (int e = 0; e < NS; e++) {
        const float* w = rw + e * HS;
        float p = 0.f;
        #pragma unroll
        for (int j = 0; j < 16; j++) p = fmaf(hv[j], w[lane + j * 32], p);
        logit[e] = warp_sum(p);
    }
    if (lane == 0) {
        float mx = fmaxf(logit[0], logit[1]);
        float e0 = expf(logit[0] - mx), e1 = expf(logit[1] - mx);
        float inv = 1.f / (e0 + e1);
        g_sp[token * NS + 0] = e0 * inv;
        g_sp[token * NS + 1] = e1 * inv;
    }
}

// ---------------- pooling + head ----------------
__global__ void pool_mean_kernel() {
    int b = blockIdx.x, d = threadIdx.x;
    float s = 0.f;
    for (int t = 0; t < SEQ; t++) s += g_h[((size_t)b * SEQ + t) * HS + d];
    g_pool[b * HS + d] = s * (1.f / SEQ);
}

__global__ __launch_bounds__(128) void cls_head_kernel(
    const float* __restrict__ w, const float* __restrict__ bias, float* __restrict__ out)
{
    int n = blockIdx.x, b = blockIdx.y;
    int tid = threadIdx.x;
    __shared__ float sm[4];
    float p = 0.f;
    for (int j = tid; j < HS; j += 128) p = fmaf(g_pool[b * HS + j], w[n * HS + j], p);
    p = warp_sum(p);
    if ((tid & 31) == 0) sm[tid >> 5] = p;
    __syncthreads();
    if (tid == 0) out[b * NCLS + n] = sm[0] + sm[1] + sm[2] + sm[3] + bias[n];
}

// ---------------- host-side launch helpers ----------------
static void launch_gemm(int act, const float* A, const float* W, const float* bias,
                        float* C, int M, int N, int K,
                        const int* gidx = nullptr, const int* mcnt = nullptr)
{
    dim3 grid(N / 64, (M + 127) / 128);
    if (act == 0)      tgemm<0, 0, 0><<<grid, 256>>>(A, W, bias, C, M, N, K, gidx, mcnt, nullptr, nullptr, 0);
    else if (act == 1) tgemm<0, 1, 0><<<grid, 256>>>(A, W, bias, C, M, N, K, gidx, mcnt, nullptr, nullptr, 0);
    else               tgemm<0, 2, 0><<<grid, 256>>>(A, W, bias, C, M, N, K, gidx, mcnt, nullptr, nullptr, 0);
}

static void launch_gemm_scatter(const float* A, const float* W, const float* bias,
                                float* C, int M, int N, int K,
                                const int* mcnt, const int* sidx,
                                const float* wv, int ws)
{
    dim3 grid(N / 64, (M + 127) / 128);
    tgemm<0, 0, 1><<<grid, 256>>>(A, W, bias, C, M, N, K, nullptr, mcnt, sidx, wv, ws);
}

extern "C" void kernel_launch(void* const* d_in, const int* in_sizes, int n_in,
                              void* d_out, int out_size)
{
    const float* x         = (const float*)d_in[0];
    const float* tok_w1    = (const float*)d_in[1];
    const float* tok_b1    = (const float*)d_in[2];
    const float* tok_w2    = (const float*)d_in[3];
    const float* tok_b2    = (const float*)d_in[4];
    const float* proj_w    = (const float*)d_in[5];
    const float* proj_b    = (const float*)d_in[6];
    const float* attn_wqkv = (const float*)d_in[7];
    const float* attn_bqkv = (const float*)d_in[8];
    const float* attn_wo   = (const float*)d_in[9];
    const float* attn_bo   = (const float*)d_in[10];
    const float* ln1_g     = (const float*)d_in[11];
    const float* ln1_b     = (const float*)d_in[12];
    const float* spec_rw   = (const float*)d_in[13];
    const float* spec_f1w  = (const float*)d_in[14];
    const float* spec_f1b  = (const float*)d_in[15];
    const float* spec_f2w  = (const float*)d_in[16];
    const float* spec_f2b  = (const float*)d_in[17];
    const float* shr_rw    = (const float*)d_in[18];
    const float* shr_f1w   = (const float*)d_in[19];
    const float* shr_f1b   = (const float*)d_in[20];
    const float* shr_f2w   = (const float*)d_in[21];
    const float* shr_f2b   = (const float*)d_in[22];
    const float* lnm_g     = (const float*)d_in[23];
    const float* lnm_b     = (const float*)d_in[24];
    const float* ln2_g     = (const float*)d_in[25];
    const float* ln2_b     = (const float*)d_in[26];
    const float* cls_w     = (const float*)d_in[27];
    const float* cls_b     = (const float*)d_in[28];
    float* out = (float*)d_out;

    float* pt;      cudaGetSymbolAddress((void**)&pt, g_t);
    float* pz1;     cudaGetSymbolAddress((void**)&pz1, g_z1);
    float* pz;      cudaGetSymbolAddress((void**)&pz, g_z);
    float* ph;      cudaGetSymbolAddress((void**)&ph, g_h);
    float* pqkv;    cudaGetSymbolAddress((void**)&pqkv, g_qkv);
    float* pscores; cudaGetSymbolAddress((void**)&pscores, g_scores);
    float* pattno;  cudaGetSymbolAddress((void**)&pattno, g_attno);
    float* pa;      cudaGetSymbolAddress((void**)&pa, g_a);
    float* pspec;   cudaGetSymbolAddress((void**)&pspec, g_spec);
    float* pm;      cudaGetSymbolAddress((void**)&pm, g_m);
    float* phid;    cudaGetSymbolAddress((void**)&phid, g_hid);
    float* psp;     cudaGetSymbolAddress((void**)&psp, g_sp);
    float* pewt;    cudaGetSymbolAddress((void**)&pewt, g_ewt);
    int* peidx;     cudaGetSymbolAddress((void**)&peidx, g_eidx);
    int* pecnt;     cudaGetSymbolAddress((void**)&pecnt, g_ecnt);

    // ---- tokenizer + projection ----
    patchify_kernel<<<(NT * PD + 255) / 256, 256>>>(x);
    launch_gemm(1, pt,  tok_w1, tok_b1, pz1, NT, SF, PD);
    launch_gemm(1, pz1, tok_w2, tok_b2, pz,  NT, ED, SF);
    add_pe_kernel<<<(NT * ED + 255) / 256, 256>>>();
    launch_gemm(0, pz,  proj_w, proj_b, ph,  NT, HS, ED);

    // ---- transformer layers ----
    for (int l = 0; l < NLAY; l++) {
        launch_gemm(0, ph, attn_wqkv + (size_t)l * 3 * HS * HS, attn_bqkv + (size_t)l * 3 * HS,
                    pqkv, NT, 3 * HS, HS);
        // scores = Q @ K^T  (batched over 64 b*h)
        tgemm<1, 0, 0><<<dim3(SEQ / 64, SEQ / 128, NB * NHD), 256>>>(
            pqkv, nullptr, nullptr, pscores, SEQ, SEQ, HDIM,
            nullptr, nullptr, nullptr, nullptr, 0);
        attn_softmax_kernel<<<dim3(SEQ, NB * NHD), 256>>>();
        // attno = softmax(scores) @ V
        tgemm<2, 0, 0><<<dim3(HDIM / 64, SEQ / 128, NB * NHD), 256>>>(
            pscores, pqkv, nullptr, pattno, SEQ, HDIM, SEQ,
            nullptr, nullptr, nullptr, nullptr, 0);
        launch_gemm(0, pattno, attn_wo + (size_t)l * HS * HS, attn_bo + (size_t)l * HS,
                    pa, NT, HS, HS);
        ln_add_kernel<<<NT, 128>>>(ph, pa, ln1_g + l * HS, ln1_b + l * HS, ph);

        // MoE
        cudaMemsetAsync(pecnt, 0, NE * sizeof(int));
        cudaMemsetAsync(pspec, 0, (size_t)NT * HS * sizeof(float));
        route_spec_kernel<<<NT / 8, 256>>>(spec_rw + (size_t)l * NE * HS);
        for (int e = 0; e < NE; e++) {
            const float* f1w = spec_f1w + (size_t)(l * NE + e) * FF * HS;
            const float* f1b = spec_f1b + (size_t)(l * NE + e) * FF;
            const float* f2w = spec_f2w + (size_t)(l * NE + e) * HS * FF;
            const float* f2b = spec_f2b + (size_t)(l * NE + e) * HS;
            launch_gemm(2, ph, f1w, f1b, phid, NT, FF, HS, peidx + e * NT, pecnt + e);
            launch_gemm_scatter(phid, f2w, f2b, pspec, NT, HS, FF,
                                pecnt + e, peidx + e * NT, pewt + e * NT, 1);
        }
        route_shared_kernel<<<NT / 8, 256>>>(shr_rw + (size_t)l * NS * HS);
        for (int e = 0; e < NS; e++) {
            const float* f1w = shr_f1w + (size_t)(l * NS + e) * FF * HS;
            const float* f1b = shr_f1b + (size_t)(l * NS + e) * FF;
            const float* f2w = shr_f2w + (size_t)(l * NS + e) * HS * FF;
            const float* f2b = shr_f2b + (size_t)(l * NS + e) * HS;
            launch_gemm(2, ph, f1w, f1b, phid, NT, FF, HS);
            launch_gemm_scatter(phid, f2w, f2b, pspec, NT, HS, FF,
                                nullptr, nullptr, psp + e, NS);
        }
        ln_add_kernel<<<NT, 128>>>(ph, pspec, lnm_g + l * HS, lnm_b + l * HS, pm);
        ln_add_kernel<<<NT, 128>>>(ph, pm, ln2_g + l * HS, ln2_b + l * HS, ph);
    }

    // ---- head ----
    pool_mean_kernel<<<NB, HS>>>();
    cls_head_kernel<<<dim3(NCLS, NB), 128>>>(cls_w, cls_b, out);
}

// round 8
// speedup vs baseline: 3.3443x; 1.6089x over previous
#include <cuda_runtime.h>
#include <cuda_bf16.h>
#include <stdint.h>
#include <math.h>

// ---------------- problem constants ----------------
#define NB    16
#define NCH   5
#define HIMG  256
#define WIMG  256
#define PP    8
#define SEQ   1024
#define NT    16384
#define PD    320
#define SF    64
#define ED    128
#define HS    512
#define NHD   4
#define HDIM  128
#define FF    2048
#define NE    6
#define NS    2
#define NLAY  4
#define NCLS  2

#define TS    40        // smem k-stride (bf16 elems): 80B rows, 16B aligned, ldmatrix conflict-free
#define ABYTES 10240    // 128*TS*2
#define WBYTES 5120     // 64*TS*2
#define BUFBYTES 30720  // 2*ABYTES + 2*WBYTES
#define SMEM_TOTAL (2*BUFBYTES)

// ---------------- fp32 scratch ----------------
__device__ float g_z[NT * ED];
__device__ float g_h[NT * HS];
__device__ float g_scores[(size_t)NB * NHD * SEQ * SEQ];
__device__ float g_a[NT * HS];
__device__ float g_spec[NT * HS];
__device__ float g_m[NT * HS];
__device__ float g_sp[NT * NS];
__device__ int   g_eidx[NE * NT];
__device__ float g_ewt[NE * NT];
__device__ int   g_ecnt[NE];
__device__ float g_pool[NB * HS];

// ---------------- bf16 split activations ----------------
__device__ __nv_bfloat16 b_t_hi[NT * PD],  b_t_lo[NT * PD];
__device__ __nv_bfloat16 b_z1_hi[NT * SF], b_z1_lo[NT * SF];
__device__ __nv_bfloat16 b_z_hi[NT * ED],  b_z_lo[NT * ED];
__device__ __nv_bfloat16 b_h_hi[NT * HS],  b_h_lo[NT * HS];
__device__ __nv_bfloat16 b_qkv_hi[NT * 3 * HS], b_qkv_lo[NT * 3 * HS];
__device__ __nv_bfloat16 b_sc_hi[(size_t)NB * NHD * SEQ * SEQ];
__device__ __nv_bfloat16 b_sc_lo[(size_t)NB * NHD * SEQ * SEQ];
__device__ __nv_bfloat16 b_at_hi[NT * HS], b_at_lo[NT * HS];
__device__ __nv_bfloat16 b_hid_hi[NT * FF], b_hid_lo[NT * FF];

// ---------------- bf16 split weights ----------------
__device__ __nv_bfloat16 w_tok1_hi[SF * PD], w_tok1_lo[SF * PD];
__device__ __nv_bfloat16 w_tok2_hi[ED * SF], w_tok2_lo[ED * SF];
__device__ __nv_bfloat16 w_proj_hi[HS * ED], w_proj_lo[HS * ED];
__device__ __nv_bfloat16 w_qkv_hi[NLAY * 3 * HS * HS], w_qkv_lo[NLAY * 3 * HS * HS];
__device__ __nv_bfloat16 w_wo_hi[NLAY * HS * HS], w_wo_lo[NLAY * HS * HS];
__device__ __nv_bfloat16 w_sf1_hi[NLAY * NE * FF * HS], w_sf1_lo[NLAY * NE * FF * HS];
__device__ __nv_bfloat16 w_sf2_hi[NLAY * NE * HS * FF], w_sf2_lo[NLAY * NE * HS * FF];
__device__ __nv_bfloat16 w_hf1_hi[NLAY * NS * FF * HS], w_hf1_lo[NLAY * NS * FF * HS];
__device__ __nv_bfloat16 w_hf2_hi[NLAY * NS * HS * FF], w_hf2_lo[NLAY * NS * HS * FF];

// ---------------- helpers ----------------
__device__ __forceinline__ float warp_sum(float v) {
    #pragma unroll
    for (int o = 16; o; o >>= 1) v += __shfl_xor_sync(0xffffffffu, v, o);
    return v;
}
__device__ __forceinline__ float warp_max(float v) {
    #pragma unroll
    for (int o = 16; o; o >>= 1) v = fmaxf(v, __shfl_xor_sync(0xffffffffu, v, o));
    return v;
}
__device__ __forceinline__ void ldsm4(unsigned int* r, unsigned int addr) {
    asm volatile("ldmatrix.sync.aligned.m8n8.x4.shared.b16 {%0,%1,%2,%3}, [%4];"
                 : "=r"(r[0]), "=r"(r[1]), "=r"(r[2]), "=r"(r[3]) : "r"(addr));
}
__device__ __forceinline__ void mma16816(float* c, const unsigned int* a, const unsigned int* b) {
    asm volatile("mma.sync.aligned.m16n8k16.row.col.f32.bf16.bf16.f32 "
                 "{%0,%1,%2,%3}, {%4,%5,%6,%7}, {%8,%9}, {%0,%1,%2,%3};"
                 : "+f"(c[0]), "+f"(c[1]), "+f"(c[2]), "+f"(c[3])
                 : "r"(a[0]), "r"(a[1]), "r"(a[2]), "r"(a[3]), "r"(b[0]), "r"(b[1]));
}
#define CP16(dst, src) asm volatile("cp.async.cg.shared.global [%0], [%1], 16;" :: "r"(dst), "l"(src))
#define CP_COMMIT() asm volatile("cp.async.commit_group;")

__device__ __forceinline__ void split2(float a, float b,
                                       __nv_bfloat16* hi, __nv_bfloat16* lo) {
    __nv_bfloat162 hp, lp;
    hp.x = __float2bfloat16(a); hp.y = __float2bfloat16(b);
    lp.x = __float2bfloat16(a - __bfloat162float(hp.x));
    lp.y = __float2bfloat16(b - __bfloat162float(hp.y));
    *(__nv_bfloat162*)hi = hp;
    *(__nv_bfloat162*)lo = lp;
}

// ---------------- weight/act split kernel (vectorized) ----------------
__global__ void split_kernel(const float4* __restrict__ src,
                             __nv_bfloat16* __restrict__ hi,
                             __nv_bfloat16* __restrict__ lo, int n4) {
    int i = blockIdx.x * blockDim.x + threadIdx.x;
    if (i >= n4) return;
    float4 v = src[i];
    split2(v.x, v.y, hi + i * 4,     lo + i * 4);
    split2(v.z, v.w, hi + i * 4 + 2, lo + i * 4 + 2);
}

// ---------------- patch extraction (writes split) ----------------
__global__ void patchify_kernel(const float* __restrict__ x) {
    int idx = blockIdx.x * blockDim.x + threadIdx.x;
    if (idx >= NT * PD) return;
    int n = idx / PD, f = idx % PD;
    int b = n / SEQ, s = n % SEQ;
    int sh = s >> 5, sw = s & 31;
    int c = f >> 6, r = f & 63;
    int pi = r >> 3, pj = r & 7;
    float v = x[(((size_t)(b * NCH + c) * HIMG + (sh * PP + pi)) * WIMG) + (sw * PP + pj)];
    __nv_bfloat16 h = __float2bfloat16(v);
    b_t_hi[idx] = h;
    b_t_lo[idx] = __float2bfloat16(v - __bfloat162float(h));
}

// ---------------- positional encoding add (reads fp32 z, writes split) ----------------
__global__ void add_pe_kernel() {
    int idx = blockIdx.x * blockDim.x + threadIdx.x;
    if (idx >= NT * ED) return;
    int n = idx >> 7, d = idx & 127;
    int s = n & (SEQ - 1);
    int i2 = d & ~1;
    float div = expf(-(float)i2 * (9.2103403719761836f / (float)ED));
    float arg = (float)s * div;
    float pe = (d & 1) ? cosf(arg) : sinf(arg);
    float v = g_z[idx] + pe;
    __nv_bfloat16 h = __float2bfloat16(v);
    b_z_hi[idx] = h;
    b_z_lo[idx] = __float2bfloat16(v - __bfloat162float(h));
}

// ================= tensor-core GEMM (bf16 split inputs, cp.async double-buffered) =================
// MODE 0: generic TN. MODE 1: QK^T batched. MODE 2: AV batched.
// OUT 0: fp32 C. OUT 1: split bf16 (Chi/Clo). OUT 2: both. SCATTER: fp32 += wgt*(acc+bias).
template<int MODE, int ACT, int SCATTER, int OUT>
__global__ __launch_bounds__(256) void tgemm(
    const __nv_bfloat16* __restrict__ Ahi, const __nv_bfloat16* __restrict__ Alo,
    const __nv_bfloat16* __restrict__ Whi, const __nv_bfloat16* __restrict__ Wlo,
    const float* __restrict__ bias, float* __restrict__ C,
    __nv_bfloat16* __restrict__ Chi, __nv_bfloat16* __restrict__ Clo,
    int M, int N, int K,
    const int* __restrict__ gidx, const int* __restrict__ mcnt,
    const int* __restrict__ sidx, const float* __restrict__ wv, int ws)
{
    const __nv_bfloat16 *Abh, *Abl, *Wbh, *Wbl;
    int lda, ldw, ldc;
    size_t cbase = 0;
    if (MODE == 1) {
        int z = blockIdx.z; int b = z >> 2, h = z & 3;
        size_t qo = (size_t)b * SEQ * (3 * HS) + h * HDIM;
        Abh = Ahi + qo;            Abl = Alo + qo;            lda = 3 * HS;
        Wbh = Ahi + qo + HS;       Wbl = Alo + qo + HS;       ldw = 3 * HS;
        cbase = (size_t)z * SEQ * SEQ;                         ldc = SEQ;
    } else if (MODE == 2) {
        int z = blockIdx.z; int b = z >> 2, h = z & 3;
        size_t so = (size_t)z * SEQ * SEQ;
        size_t vo = (size_t)b * SEQ * (3 * HS) + 2 * HS + h * HDIM;
        Abh = Ahi + so; Abl = Alo + so;  lda = SEQ;
        Wbh = Whi + vo; Wbl = Wlo + vo;  ldw = 3 * HS;
        cbase = (size_t)b * SEQ * HS + h * HDIM;  ldc = HS;
    } else {
        Abh = Ahi; Abl = Alo; Wbh = Whi; Wbl = Wlo;
        lda = K; ldw = K; ldc = N;
    }

    int Mr = (MODE == 0 && mcnt) ? *mcnt : M;
    int m0 = blockIdx.y * 128;
    int n0 = blockIdx.x * 64;
    if (m0 >= Mr) return;

    extern __shared__ __align__(16) char smem[];
    __shared__ int ridx[128];

    int tid = threadIdx.x;
    int warp = tid >> 5, L = tid & 31;
    int warp_m = warp >> 1, warp_n = warp & 1;

    if (tid < 128) {
        int r = m0 + tid;
        if (r > Mr - 1) r = Mr - 1;
        ridx[tid] = (MODE == 0 && gidx) ? gidx[r] : r;
    }
    __syncthreads();

    unsigned int sbase = (unsigned int)__cvta_generic_to_shared(smem);

    // ldmatrix per-lane offsets (element units)
    int rowA = ((L >> 3) & 1) * 8 + (L & 7);
    int kA   = ((L >> 4) & 1) * 8;
    int rowB = ((L >> 4) & 1) * 8 + (L & 7);
    int kB   = ((L >> 3) & 1) * 8;
    int offA[2], offB[2];
    #pragma unroll
    for (int mi = 0; mi < 2; mi++) offA[mi] = (warp_m * 32 + mi * 16 + rowA) * TS + kA;
    #pragma unroll
    for (int nb = 0; nb < 2; nb++) offB[nb] = (warp_n * 32 + nb * 16 + rowB) * TS + kB;

    auto stage = [&](int buf, int kk) {
        unsigned int aH = sbase + buf * BUFBYTES;
        unsigned int aL = aH + ABYTES;
        unsigned int wH = aH + 2 * ABYTES;
        unsigned int wL = wH + WBYTES;
        #pragma unroll
        for (int i = 0; i < 2; i++) {
            int f = tid + i * 256;
            int r = f >> 2, c8 = (f & 3) * 8;
            size_t so = (size_t)ridx[r] * lda + kk + c8;
            unsigned int d = (unsigned int)((r * TS + c8) * 2);
            CP16(aH + d, Abh + so);
            CP16(aL + d, Abl + so);
        }
        if (MODE == 2) {
            // V transposed staging: scalar bf16x2 loads
            __nv_bfloat16* swh = (__nv_bfloat16*)(smem + buf * BUFBYTES + 2 * ABYTES);
            __nv_bfloat16* swl = (__nv_bfloat16*)(smem + buf * BUFBYTES + 2 * ABYTES + WBYTES);
            #pragma unroll
            for (int j = 0; j < 4; j++) {
                int idx = tid + j * 256;      // 1024 bf16x2 pairs
                int k = idx >> 5, n2 = (idx & 31) * 2;
                size_t so = (size_t)(kk + k) * ldw + n0 + n2;
                __nv_bfloat162 vh = *(const __nv_bfloat162*)(Wbh + so);
                __nv_bfloat162 vl = *(const __nv_bfloat162*)(Wbl + so);
                swh[n2 * TS + k] = vh.x; swh[(n2 + 1) * TS + k] = vh.y;
                swl[n2 * TS + k] = vl.x; swl[(n2 + 1) * TS + k] = vl.y;
            }
        } else {
            int r = tid >> 2, c8 = (tid & 3) * 8;
            size_t so = (size_t)(n0 + r) * ldw + kk + c8;
            unsigned int d = (unsigned int)((r * TS + c8) * 2);
            CP16(wH + d, Wbh + so);
            CP16(wL + d, Wbl + so);
        }
    };

    float acc[2][4][4] = {};
    int KT = K / 32;

    stage(0, 0);
    CP_COMMIT();

    for (int kt = 0; kt < KT; kt++) {
        int cur = kt & 1;
        if (kt + 1 < KT) {
            stage(cur ^ 1, (kt + 1) * 32);
            CP_COMMIT();
            asm volatile("cp.async.wait_group 1;");
        } else {
            asm volatile("cp.async.wait_group 0;");
        }
        __syncthreads();

        unsigned int aH = sbase + cur * BUFBYTES;
        unsigned int aL = aH + ABYTES;
        unsigned int wH = aH + 2 * ABYTES;
        unsigned int wL = wH + WBYTES;

        #pragma unroll
        for (int ks = 0; ks < 32; ks += 16) {
            unsigned int ah[2][4], al[2][4], bh[2][4], bl[2][4];
            #pragma unroll
            for (int mi = 0; mi < 2; mi++) {
                ldsm4(ah[mi], aH + (unsigned int)(offA[mi] + ks) * 2u);
                ldsm4(al[mi], aL + (unsigned int)(offA[mi] + ks) * 2u);
            }
            #pragma unroll
            for (int nb = 0; nb < 2; nb++) {
                ldsm4(bh[nb], wH + (unsigned int)(offB[nb] + ks) * 2u);
                ldsm4(bl[nb], wL + (unsigned int)(offB[nb] + ks) * 2u);
            }
            #pragma unroll
            for (int mi = 0; mi < 2; mi++)
                #pragma unroll
                for (int ni = 0; ni < 4; ni++) {
                    int nb = ni >> 1, sel = (ni & 1) * 2;
                    mma16816(acc[mi][ni], ah[mi], &bh[nb][sel]);
                    mma16816(acc[mi][ni], ah[mi], &bl[nb][sel]);
                    mma16816(acc[mi][ni], al[mi], &bh[nb][sel]);
                }
        }
        __syncthreads();
    }

    // ---- epilogue ----
    #pragma unroll
    for (int mi = 0; mi < 2; mi++) {
        #pragma unroll
        for (int hh = 0; hh < 2; hh++) {
            int m = m0 + warp_m * 32 + mi * 16 + (L >> 2) + hh * 8;
            if (m >= Mr) continue;
            int srow = 0; float wgt = 0.f;
            if (SCATTER) {
                srow = sidx ? sidx[m] : m;
                wgt = wv[(size_t)m * ws];
            }
            #pragma unroll
            for (int ni = 0; ni < 4; ni++) {
                int n = n0 + warp_n * 32 + ni * 8 + (L & 3) * 2;
                float v0 = acc[mi][ni][hh * 2 + 0];
                float v1 = acc[mi][ni][hh * 2 + 1];
                if (MODE == 0 && bias) { v0 += bias[n]; v1 += bias[n + 1]; }
                if (ACT == 1) { v0 = fmaxf(v0, 0.f); v1 = fmaxf(v1, 0.f); }
                if (ACT == 2) {
                    v0 = 0.5f * v0 * (1.f + erff(v0 * 0.70710678118654752f));
                    v1 = 0.5f * v1 * (1.f + erff(v1 * 0.70710678118654752f));
                }
                size_t ci = cbase + (size_t)(SCATTER ? srow : m) * ldc + n;
                if (SCATTER) {
                    C[ci] += wgt * v0;
                    C[ci + 1] += wgt * v1;
                } else {
                    if (OUT == 0 || OUT == 2) { C[ci] = v0; C[ci + 1] = v1; }
                    if (OUT == 1 || OUT == 2) split2(v0, v1, Chi + ci, Clo + ci);
                }
            }
        }
    }
}

// ---------------- attention softmax (reads fp32, writes split bf16) ----------------
__global__ __launch_bounds__(256) void attn_softmax_kernel() {
    size_t base = ((size_t)blockIdx.y * SEQ + blockIdx.x) * SEQ;
    const float* row = g_scores + base;
    const float scale = 0.08838834764831845f;
    int tid = threadIdx.x;
    __shared__ float sm[8];

    float v[4];
    float mx = -1e30f;
    #pragma unroll
    for (int i = 0; i < 4; i++) { v[i] = row[tid + i * 256] * scale; mx = fmaxf(mx, v[i]); }
    mx = warp_max(mx);
    if ((tid & 31) == 0) sm[tid >> 5] = mx;
    __syncthreads();
    float bm = sm[0];
    #pragma unroll
    for (int i = 1; i < 8; i++) bm = fmaxf(bm, sm[i]);
    __syncthreads();

    float s = 0.f;
    #pragma unroll
    for (int i = 0; i < 4; i++) { v[i] = expf(v[i] - bm); s += v[i]; }
    s = warp_sum(s);
    if ((tid & 31) == 0) sm[tid >> 5] = s;
    __syncthreads();
    float tot = 0.f;
    #pragma unroll
    for (int i = 0; i < 8; i++) tot += sm[i];
    float inv = 1.f / tot;
    #pragma unroll
    for (int i = 0; i < 4; i++) {
        float p = v[i] * inv;
        size_t idx = base + tid + i * 256;
        __nv_bfloat16 h = __float2bfloat16(p);
        b_sc_hi[idx] = h;
        b_sc_lo[idx] = __float2bfloat16(p - __bfloat162float(h));
    }
}

// ---------------- fused residual-add + layernorm (optional split out) ----------------
__global__ __launch_bounds__(128) void ln_add_kernel(
    const float* __restrict__ X, const float* __restrict__ Y,
    const float* __restrict__ gam, const float* __restrict__ bet,
    float* __restrict__ O, __nv_bfloat16* __restrict__ Ohi, __nv_bfloat16* __restrict__ Olo)
{
    size_t base = (size_t)blockIdx.x * HS;
    int tid = threadIdx.x;
    __shared__ float sm[4];
    float v[4];
    #pragma unroll
    for (int i = 0; i < 4; i++) { int d = tid + i * 128; v[i] = X[base + d] + Y[base + d]; }
    float s = v[0] + v[1] + v[2] + v[3];
    s = warp_sum(s);
    if ((tid & 31) == 0) sm[tid >> 5] = s;
    __syncthreads();
    float mean = (sm[0] + sm[1] + sm[2] + sm[3]) * (1.f / HS);
    __syncthreads();
    float q = 0.f;
    #pragma unroll
    for (int i = 0; i < 4; i++) { float d = v[i] - mean; q += d * d; }
    q = warp_sum(q);
    if ((tid & 31) == 0) sm[tid >> 5] = q;
    __syncthreads();
    float var = (sm[0] + sm[1] + sm[2] + sm[3]) * (1.f / HS);
    float inv = rsqrtf(var + 1e-5f);
    #pragma unroll
    for (int i = 0; i < 4; i++) {
        int d = tid + i * 128;
        float o = (v[i] - mean) * inv * gam[d] + bet[d];
        O[base + d] = o;
        if (Ohi) {
            __nv_bfloat16 h = __float2bfloat16(o);
            Ohi[base + d] = h;
            Olo[base + d] = __float2bfloat16(o - __bfloat162float(h));
        }
    }
}

// ---------------- routers ----------------
__global__ __launch_bounds__(256) void route_spec_kernel(const float* __restrict__ rw) {
    int warp = threadIdx.x >> 5, lane = threadIdx.x & 31;
    int token = blockIdx.x * 8 + warp;
    const float* hrow = g_h + (size_t)token * HS;
    float hv[16];
    #pragma unroll
    for (int j = 0; j < 16; j++) hv[j] = hrow[lane + j * 32];
    float logit[NE];
    #pragma unroll
    for (int e = 0; e < NE; e++) {
        const float* w = rw + e * HS;
        float p = 0.f;
        #pragma unroll
        for (int j = 0; j < 16; j++) p = fmaf(hv[j], w[lane + j * 32], p);
        logit[e] = warp_sum(p);
    }
    if (lane == 0) {
        float mx = logit[0];
        #pragma unroll
        for (int e = 1; e < NE; e++) mx = fmaxf(mx, logit[e]);
        float pr[NE], s = 0.f;
        #pragma unroll
        for (int e = 0; e < NE; e++) { pr[e] = expf(logit[e] - mx); s += pr[e]; }
        #pragma unroll
        for (int e = 0; e < NE; e++) pr[e] /= s;
        int i1 = 0;
        #pragma unroll
        for (int e = 1; e < NE; e++) if (pr[e] > pr[i1]) i1 = e;
        int i2 = (i1 == 0) ? 1 : 0;
        #pragma unroll
        for (int e = 0; e < NE; e++) if (e != i1 && pr[e] > pr[i2]) i2 = e;
        float den = pr[i1] + pr[i2] + 1e-9f;
        float w1 = pr[i1] / den, w2 = pr[i2] / den;
        int p1 = atomicAdd(&g_ecnt[i1], 1);
        g_eidx[i1 * NT + p1] = token; g_ewt[i1 * NT + p1] = w1;
        int p2 = atomicAdd(&g_ecnt[i2], 1);
        g_eidx[i2 * NT + p2] = token; g_ewt[i2 * NT + p2] = w2;
    }
}

__global__ __launch_bounds__(256) void route_shared_kernel(const float* __restrict__ rw) {
    int warp = threadIdx.x >> 5, lane = threadIdx.x & 31;
    int token = blockIdx.x * 8 + warp;
    const float* hrow = g_h + (size_t)token * HS;
    float hv[16];
    #pragma unroll
    for (int j = 0; j < 16; j++) hv[j] = hrow[lane + j * 32];
    float logit[NS];
    #pragma unroll
    for (int e = 0; e < NS; e++) {
        const float* w = rw + e * HS;
        float p = 0.f;
        #pragma unroll
        for (int j = 0; j < 16; j++) p = fmaf(hv[j], w[lane + j * 32], p);
        logit[e] = warp_sum(p);
    }
    if (lane == 0) {
        float mx = fmaxf(logit[0], logit[1]);
        float e0 = expf(logit[0] - mx), e1 = expf(logit[1] - mx);
        float inv = 1.f / (e0 + e1);
        g_sp[token * NS + 0] = e0 * inv;
        g_sp[token * NS + 1] = e1 * inv;
    }
}

// ---------------- pooling + head ----------------
__global__ void pool_mean_kernel() {
    int b = blockIdx.x, d = threadIdx.x;
    float s = 0.f;
    for (int t = 0; t < SEQ; t++) s += g_h[((size_t)b * SEQ + t) * HS + d];
    g_pool[b * HS + d] = s * (1.f / SEQ);
}

__global__ __launch_bounds__(128) void cls_head_kernel(
    const float* __restrict__ w, const float* __restrict__ bias, float* __restrict__ out)
{
    int n = blockIdx.x, b = blockIdx.y;
    int tid = threadIdx.x;
    __shared__ float sm[4];
    float p = 0.f;
    for (int j = tid; j < HS; j += 128) p = fmaf(g_pool[b * HS + j], w[n * HS + j], p);
    p = warp_sum(p);
    if ((tid & 31) == 0) sm[tid >> 5] = p;
    __syncthreads();
    if (tid == 0) out[b * NCLS + n] = sm[0] + sm[1] + sm[2] + sm[3] + bias[n];
}

// ---------------- host helpers ----------------
typedef __nv_bfloat16 bf16;

static void split_arr(const float* src, bf16* hi, bf16* lo, size_t n) {
    int n4 = (int)(n / 4);
    split_kernel<<<(n4 + 255) / 256, 256>>>((const float4*)src, hi, lo, n4);
}

template<int MODE, int ACT, int SCATTER, int OUT>
static void launch_tg(dim3 grid,
                      const bf16* Ahi, const bf16* Alo, const bf16* Whi, const bf16* Wlo,
                      const float* bias, float* C, bf16* Chi, bf16* Clo,
                      int M, int N, int K,
                      const int* gidx = nullptr, const int* mcnt = nullptr,
                      const int* sidx = nullptr, const float* wv = nullptr, int ws = 0)
{
    cudaFuncSetAttribute(tgemm<MODE, ACT, SCATTER, OUT>,
                         cudaFuncAttributeMaxDynamicSharedMemorySize, SMEM_TOTAL);
    tgemm<MODE, ACT, SCATTER, OUT><<<grid, 256, SMEM_TOTAL>>>(
        Ahi, Alo, Whi, Wlo, bias, C, Chi, Clo, M, N, K, gidx, mcnt, sidx, wv, ws);
}

#define SYM(T, p, s) T* p; cudaGetSymbolAddress((void**)&p, s)

extern "C" void kernel_launch(void* const* d_in, const int* in_sizes, int n_in,
                              void* d_out, int out_size)
{
    const float* x         = (const float*)d_in[0];
    const float* tok_w1    = (const float*)d_in[1];
    const float* tok_b1    = (const float*)d_in[2];
    const float* tok_w2    = (const float*)d_in[3];
    const float* tok_b2    = (const float*)d_in[4];
    const float* proj_w    = (const float*)d_in[5];
    const float* proj_b    = (const float*)d_in[6];
    const float* attn_wqkv = (const float*)d_in[7];
    const float* attn_bqkv = (const float*)d_in[8];
    const float* attn_wo   = (const float*)d_in[9];
    const float* attn_bo   = (const float*)d_in[10];
    const float* ln1_g     = (const float*)d_in[11];
    const float* ln1_b     = (const float*)d_in[12];
    const float* spec_rw   = (const float*)d_in[13];
    const float* spec_f1w  = (const float*)d_in[14];
    const float* spec_f1b  = (const float*)d_in[15];
    const float* spec_f2w  = (const float*)d_in[16];
    const float* spec_f2b  = (const float*)d_in[17];
    const float* shr_rw    = (const float*)d_in[18];
    const float* shr_f1w   = (const float*)d_in[19];
    const float* shr_f1b   = (const float*)d_in[20];
    const float* shr_f2w   = (const float*)d_in[21];
    const float* shr_f2b   = (const float*)d_in[22];
    const float* lnm_g     = (const float*)d_in[23];
    const float* lnm_b     = (const float*)d_in[24];
    const float* ln2_g     = (const float*)d_in[25];
    const float* ln2_b     = (const float*)d_in[26];
    const float* cls_w     = (const float*)d_in[27];
    const float* cls_b     = (const float*)d_in[28];
    float* out = (float*)d_out;

    SYM(float, pz, g_z);       SYM(float, ph, g_h);      SYM(float, pscores, g_scores);
    SYM(float, pa, g_a);       SYM(float, pspec, g_spec); SYM(float, pm, g_m);
    SYM(float, psp, g_sp);     SYM(float, pewt, g_ewt);  SYM(float, ppool, g_pool);
    SYM(int, peidx, g_eidx);   SYM(int, pecnt, g_ecnt);
    (void)ppool;

    SYM(bf16, t_hi, b_t_hi);   SYM(bf16, t_lo, b_t_lo);
    SYM(bf16, z1_hi, b_z1_hi); SYM(bf16, z1_lo, b_z1_lo);
    SYM(bf16, z_hi, b_z_hi);   SYM(bf16, z_lo, b_z_lo);
    SYM(bf16, h_hi, b_h_hi);   SYM(bf16, h_lo, b_h_lo);
    SYM(bf16, qkv_hi, b_qkv_hi); SYM(bf16, qkv_lo, b_qkv_lo);
    SYM(bf16, sc_hi, b_sc_hi); SYM(bf16, sc_lo, b_sc_lo);
    SYM(bf16, at_hi, b_at_hi); SYM(bf16, at_lo, b_at_lo);
    SYM(bf16, hid_hi, b_hid_hi); SYM(bf16, hid_lo, b_hid_lo);

    SYM(bf16, tw1_hi, w_tok1_hi); SYM(bf16, tw1_lo, w_tok1_lo);
    SYM(bf16, tw2_hi, w_tok2_hi); SYM(bf16, tw2_lo, w_tok2_lo);
    SYM(bf16, pw_hi, w_proj_hi);  SYM(bf16, pw_lo, w_proj_lo);
    SYM(bf16, qw_hi, w_qkv_hi);   SYM(bf16, qw_lo, w_qkv_lo);
    SYM(bf16, ow_hi, w_wo_hi);    SYM(bf16, ow_lo, w_wo_lo);
    SYM(bf16, s1_hi, w_sf1_hi);   SYM(bf16, s1_lo, w_sf1_lo);
    SYM(bf16, s2_hi, w_sf2_hi);   SYM(bf16, s2_lo, w_sf2_lo);
    SYM(bf16, h1_hi, w_hf1_hi);   SYM(bf16, h1_lo, w_hf1_lo);
    SYM(bf16, h2_hi, w_hf2_hi);   SYM(bf16, h2_lo, w_hf2_lo);

    // ---- split all weights once per launch ----
    split_arr(tok_w1, tw1_hi, tw1_lo, (size_t)SF * PD);
    split_arr(tok_w2, tw2_hi, tw2_lo, (size_t)ED * SF);
    split_arr(proj_w, pw_hi, pw_lo, (size_t)HS * ED);
    split_arr(attn_wqkv, qw_hi, qw_lo, (size_t)NLAY * 3 * HS * HS);
    split_arr(attn_wo, ow_hi, ow_lo, (size_t)NLAY * HS * HS);
    split_arr(spec_f1w, s1_hi, s1_lo, (size_t)NLAY * NE * FF * HS);
    split_arr(spec_f2w, s2_hi, s2_lo, (size_t)NLAY * NE * HS * FF);
    split_arr(shr_f1w, h1_hi, h1_lo, (size_t)NLAY * NS * FF * HS);
    split_arr(shr_f2w, h2_hi, h2_lo, (size_t)NLAY * NS * HS * FF);

    // ---- tokenizer + projection ----
    patchify_kernel<<<(NT * PD + 255) / 256, 256>>>(x);
    launch_tg<0, 1, 0, 1>(dim3(SF / 64, NT / 128), t_hi, t_lo, tw1_hi, tw1_lo,
                          tok_b1, nullptr, z1_hi, z1_lo, NT, SF, PD);
    launch_tg<0, 1, 0, 0>(dim3(ED / 64, NT / 128), z1_hi, z1_lo, tw2_hi, tw2_lo,
                          tok_b2, pz, nullptr, nullptr, NT, ED, SF);
    add_pe_kernel<<<(NT * ED + 255) / 256, 256>>>();
    launch_tg<0, 0, 0, 2>(dim3(HS / 64, NT / 128), z_hi, z_lo, pw_hi, pw_lo,
                          proj_b, ph, h_hi, h_lo, NT, HS, ED);

    // ---- transformer layers ----
    for (int l = 0; l < NLAY; l++) {
        launch_tg<0, 0, 0, 1>(dim3(3 * HS / 64, NT / 128),
                              h_hi, h_lo, qw_hi + (size_t)l * 3 * HS * HS, qw_lo + (size_t)l * 3 * HS * HS,
                              attn_bqkv + (size_t)l * 3 * HS, nullptr, qkv_hi, qkv_lo,
                              NT, 3 * HS, HS);
        launch_tg<1, 0, 0, 0>(dim3(SEQ / 64, SEQ / 128, NB * NHD),
                              qkv_hi, qkv_lo, nullptr, nullptr,
                              nullptr, pscores, nullptr, nullptr, SEQ, SEQ, HDIM);
        attn_softmax_kernel<<<dim3(SEQ, NB * NHD), 256>>>();
        launch_tg<2, 0, 0, 1>(dim3(HDIM / 64, SEQ / 128, NB * NHD),
                              sc_hi, sc_lo, qkv_hi, qkv_lo,
                              nullptr, nullptr, at_hi, at_lo, SEQ, HDIM, SEQ);
        launch_tg<0, 0, 0, 0>(dim3(HS / 64, NT / 128),
                              at_hi, at_lo, ow_hi + (size_t)l * HS * HS, ow_lo + (size_t)l * HS * HS,
                              attn_bo + (size_t)l * HS, pa, nullptr, nullptr, NT, HS, HS);
        ln_add_kernel<<<NT, 128>>>(ph, pa, ln1_g + l * HS, ln1_b + l * HS, ph, h_hi, h_lo);

        // MoE
        cudaMemsetAsync(pecnt, 0, NE * sizeof(int));
        cudaMemsetAsync(pspec, 0, (size_t)NT * HS * sizeof(float));
        route_spec_kernel<<<NT / 8, 256>>>(spec_rw + (size_t)l * NE * HS);
        for (int e = 0; e < NE; e++) {
            size_t wo1 = (size_t)(l * NE + e) * FF * HS;
            size_t wo2 = (size_t)(l * NE + e) * HS * FF;
            launch_tg<0, 2, 0, 1>(dim3(FF / 64, NT / 128),
                                  h_hi, h_lo, s1_hi + wo1, s1_lo + wo1,
                                  spec_f1b + (size_t)(l * NE + e) * FF,
                                  nullptr, hid_hi, hid_lo, NT, FF, HS,
                                  peidx + e * NT, pecnt + e);
            launch_tg<0, 0, 1, 0>(dim3(HS / 64, NT / 128),
                                  hid_hi, hid_lo, s2_hi + wo2, s2_lo + wo2,
                                  spec_f2b + (size_t)(l * NE + e) * HS,
                                  pspec, nullptr, nullptr, NT, HS, FF,
                                  nullptr, pecnt + e, peidx + e * NT, pewt + e * NT, 1);
        }
        route_shared_kernel<<<NT / 8, 256>>>(shr_rw + (size_t)l * NS * HS);
        for (int e = 0; e < NS; e++) {
            size_t wo1 = (size_t)(l * NS + e) * FF * HS;
            size_t wo2 = (size_t)(l * NS + e) * HS * FF;
            launch_tg<0, 2, 0, 1>(dim3(FF / 64, NT / 128),
                                  h_hi, h_lo, h1_hi + wo1, h1_lo + wo1,
                                  shr_f1b + (size_t)(l * NS + e) * FF,
                                  nullptr, hid_hi, hid_lo, NT, FF, HS);
            launch_tg<0, 0, 1, 0>(dim3(HS / 64, NT / 128),
                                  hid_hi, hid_lo, h2_hi + wo2, h2_lo + wo2,
                                  shr_f2b + (size_t)(l * NS + e) * HS,
                                  pspec, nullptr, nullptr, NT, HS, FF,
                                  nullptr, nullptr, nullptr, psp + e, NS);
        }
        ln_add_kernel<<<NT, 128>>>(ph, pspec, lnm_g + l * HS, lnm_b + l * HS, pm, nullptr, nullptr);
        ln_add_kernel<<<NT, 128>>>(ph, pm, ln2_g + l * HS, ln2_b + l * HS, ph, h_hi, h_lo);
    }

    // ---- head ----
    pool_mean_kernel<<<NB, HS>>>();
    cls_head_kernel<<<dim3(NCLS, NB), 128>>>(cls_w, cls_b, out);
}